// round 12
// baseline (speedup 1.0000x reference)
#include <cuda_runtime.h>

#define NIN     64
#define NOUT    64
#define NJ      (NIN * NOUT)       // 4096
#define NKNOTS  10
#define NBASIS  6
#define NRCP    24
#define SUB     7                  // batches per sub-tile
#define NSUB    2
#define BATCH_TILE (SUB * NSUB)    // 14
#define THREADS 512

// ---- dynamic shared layout (bytes) ----
#define SFEAT_OFF   0
#define SFEAT_BYTES (NSUB * 7 * SUB * NIN * 4)      // 25088  [buf][c][bl][i]
#define SGRID_OFF   (SFEAT_OFF + SFEAT_BYTES)
#define SGRID_BYTES (NKNOTS * 32 * 8)               // 2560
#define SRCP_OFF    (SGRID_OFF + SGRID_BYTES)
#define SRCP_BYTES  (NRCP * 32 * 8)                 // 6144
#define SNRCP_OFF   (SRCP_OFF + SRCP_BYTES)
#define SNRCP_BYTES (NRCP * 32 * 8)                 // 6144
#define SYPART_OFF  (SNRCP_OFF + SNRCP_BYTES)
#define SYPART_BYTES (NSUB * SUB * 16 * 32 * 16)    // 114688 [buf][bl][oq][lane]
#define SPART_OFF   (SYPART_OFF + SYPART_BYTES)
#define SPART_BYTES (NSUB * 112 * 2 * 16)           // 7168   [buf][item][half]
#define SMEM_TOTAL  (SPART_OFF + SPART_BYTES)       // 161792

typedef unsigned long long ull;
__device__ __forceinline__ ull pack2(float lo, float hi) {
    ull r; asm("mov.b64 %0, {%1, %2};" : "=l"(r) : "f"(lo), "f"(hi)); return r;
}
#define FMA2(d,a,b,c) asm("fma.rn.f32x2 %0, %1, %2, %3;" : "=l"(d) : "l"(a), "l"(b), "l"(c))
#define MUL2(d,a,b)   asm("mul.rn.f32x2 %0, %1, %2;"     : "=l"(d) : "l"(a), "l"(b))
#define ADD2(d,a,b)   asm("add.rn.f32x2 %0, %1, %2;"     : "=l"(d) : "l"(a), "l"(b))
#define UNPK(lo,hi,p) asm("mov.b64 {%0, %1}, %2;" : "=f"(lo), "=f"(hi) : "l"(p))
#define ABSMASK 0x7FFFFFFF7FFFFFFFULL
#define NEG1X2  0xBF800000BF800000ULL

// L2-resident accumulator + tickets (zero at load; self-reset per launch).
__device__ __align__(16) float g_splacc[NJ];
__device__ unsigned int g_ticket;
__device__ unsigned int g_done;

struct Smem {
    float  (*sfeat)[7][SUB][NIN];   // [buf][c][bl][i]
    ull    (*sgridn01)[32];         // [m][ip]
    ull    (*srcp01)[32];           // [e][ip]
    ull    (*snrcp01)[32];          // [e][ip]
    float4 (*sypart)[SUB][16][32];  // [buf][bl][oq][lane]
    float4 (*spart)[112][2];        // [buf][item][half]
};

// ---- P1: packed basis + silu for one 7-batch sub-tile (224 active threads)
__device__ __forceinline__
void p1(const Smem& S, int buf, int bstart, int batch, int t,
        const float* __restrict__ x)
{
    if (t >= SUB * 32) return;
    const int ip = t & 31;
    const int bl = t >> 5;
    int b = bstart + bl;
    float2 xv = (b < batch) ? *(const float2*)&x[(size_t)b * NIN + ip * 2]
                            : make_float2(0.f, 0.f);
    ull x01 = pack2(xv.x, xv.y);

    ull d01[NKNOTS];
    #pragma unroll
    for (int m = 0; m < NKNOTS; m++) {
        ull nk = S.sgridn01[m][ip];
        ADD2(d01[m], x01, nk);
    }
    ull bs01[9];
    {
        const ull neg1 = NEG1X2;
        float dA, dB; UNPK(dA, dB, d01[0]);
        ull gprev = pack2(dA >= 0.f ? 1.f : 0.f, dB >= 0.f ? 1.f : 0.f);
        #pragma unroll
        for (int m = 0; m < 9; m++) {
            UNPK(dA, dB, d01[m + 1]);
            ull gnext = pack2(dA >= 0.f ? 1.f : 0.f, dB >= 0.f ? 1.f : 0.f);
            FMA2(bs01[m], gnext, neg1, gprev);
            gprev = gnext;
        }
    }
    #pragma unroll
    for (int K = 1; K <= 3; K++) {
        const int off = (K == 1) ? 0 : (K == 2) ? 9 : 17;
        #pragma unroll
        for (int m = 0; m <= 8 - K; m++) {
            ull rl = S.srcp01[off + m][ip];
            ull rr = S.snrcp01[off + m + 1][ip];
            ull left, w, wb, nb;
            MUL2(left, d01[m], rl);
            MUL2(w, d01[m + K + 1], rr);
            MUL2(wb, w, bs01[m + 1]);
            FMA2(nb, left, bs01[m], wb);
            bs01[m] = nb;
        }
    }
    #pragma unroll
    for (int c = 0; c < NBASIS; c++)
        *(ull*)&S.sfeat[buf][c][bl][ip * 2] = bs01[c];
    float sA = xv.x / (1.0f + __expf(-xv.x));
    float sB = xv.y / (1.0f + __expf(-xv.y));
    *(ull*)&S.sfeat[buf][6][bl][ip * 2] = pack2(sA, sB);
}

// ---- P2: packed-FMA spl / y-partial / |spl| for one sub-tile
template <bool FULL>
__device__ __forceinline__
void p2(const Smem& S, int buf, int n, int lane, int oq,
        const ull cb01[4][NBASIS], const ull csp01[4], const ull crs01[4],
        ull acc01[4])
{
    #pragma unroll
    for (int bl = 0; bl < SUB; bl++) {
        if (!FULL && bl >= n) break;
        ull f01[7];
        #pragma unroll
        for (int c = 0; c < 7; c++)
            f01[c] = *(const ull*)&S.sfeat[buf][c][bl][lane * 2];

        float4 yp;
        float* ypp = (float*)&yp;
        #pragma unroll
        for (int q = 0; q < 4; q++) {
            ull s01;
            MUL2(s01, cb01[q][0], f01[0]);
            #pragma unroll
            for (int c = 1; c < NBASIS; c++)
                FMA2(s01, cb01[q][c], f01[c], s01);
            ull a01 = s01 & ABSMASK;
            ADD2(acc01[q], acc01[q], a01);
            ull t01;
            MUL2(t01, csp01[q], s01);
            FMA2(t01, crs01[q], f01[6], t01);
            float t0, t1; UNPK(t0, t1, t01);
            ypp[q] = t0 + t1;
        }
        S.sypart[buf][bl][oq][lane] = yp;    // fire-and-forget
    }
}

// ---- EPI1: half-lane reduction of sypart -> spart (224 active threads)
__device__ __forceinline__
void epi1(const Smem& S, int buf, int n, int t)
{
    if (t >= 112 * 2) return;
    int item = t >> 1, half = t & 1;
    int bl = item >> 4, oqr = item & 15;
    if (bl >= n) return;
    float4 s = make_float4(0.f, 0.f, 0.f, 0.f);
    int base = half * 16, rot = t & 15;
    #pragma unroll
    for (int k = 0; k < 16; k++) {
        int ls = base + ((k + rot) & 15);
        float4 v = S.sypart[buf][bl][oqr][ls];
        s.x += v.x; s.y += v.y; s.z += v.z; s.w += v.w;
    }
    S.spart[buf][item][half] = s;
}

// ---- EPI2: combine halves -> y (112 active threads)
__device__ __forceinline__
void epi2(const Smem& S, int buf, int n, int bstart, int t,
          float* __restrict__ y_out)
{
    if (t >= 112) return;
    int bl = t >> 4, oqr = t & 15;
    if (bl >= n) return;
    float4 a = S.spart[buf][t][0];
    float4 b = S.spart[buf][t][1];
    const float sc = 1.0f / NIN;
    a.x = (a.x + b.x) * sc; a.y = (a.y + b.y) * sc;
    a.z = (a.z + b.z) * sc; a.w = (a.w + b.w) * sc;
    *(float4*)&y_out[(size_t)(bstart + bl) * NOUT + oqr * 4] = a;
}

__global__ __launch_bounds__(THREADS, 1)
void kan_fused_kernel(const float* __restrict__ x,
                      const float* __restrict__ c_basis,
                      const float* __restrict__ c_spl,
                      const float* __restrict__ c_res,
                      const float* __restrict__ grid,
                      float* __restrict__ y_out,
                      float* __restrict__ reg_out,
                      int batch, float inv_batch, int nblocks)
{
    extern __shared__ __align__(16) char smem_raw[];
    Smem S;
    S.sfeat    = (float  (*)[7][SUB][NIN])(smem_raw + SFEAT_OFF);
    S.sgridn01 = (ull    (*)[32])(smem_raw + SGRID_OFF);
    S.srcp01   = (ull    (*)[32])(smem_raw + SRCP_OFF);
    S.snrcp01  = (ull    (*)[32])(smem_raw + SNRCP_OFF);
    S.sypart   = (float4 (*)[SUB][16][32])(smem_raw + SYPART_OFF);
    S.spart    = (float4 (*)[112][2])(smem_raw + SPART_OFF);

    const int t    = threadIdx.x;
    const int lane = t & 31;
    const int oq   = t >> 5;
    const int b0   = blockIdx.x * BATCH_TILE;
    const int nbl  = min(BATCH_TILE, batch - b0);
    const int n0   = min(nbl, SUB);
    const int n1   = max(0, min(nbl - SUB, SUB));

    // ---- A: tables ----
    for (int p = t; p < NKNOTS * 32; p += THREADS) {
        int ip = p & 31, m = p >> 5;
        int i0 = ip * 2;
        S.sgridn01[m][ip] = pack2(-__ldg(&grid[i0 * NKNOTS + m]),
                                  -__ldg(&grid[(i0 + 1) * NKNOTS + m]));
    }
    for (int p = t; p < NRCP * 32; p += THREADS) {
        int ip = p & 31, e = p >> 5;
        int K = (e < 9) ? 1 : (e < 17) ? 2 : 3;
        int m = (e < 9) ? e : (e < 17) ? e - 9 : e - 17;
        int i0 = ip * 2;
        float r0 = 1.0f / (__ldg(&grid[i0 * NKNOTS + m + K]) - __ldg(&grid[i0 * NKNOTS + m]));
        float r1 = 1.0f / (__ldg(&grid[(i0 + 1) * NKNOTS + m + K]) - __ldg(&grid[(i0 + 1) * NKNOTS + m]));
        S.srcp01[e][ip]  = pack2(r0, r1);
        S.snrcp01[e][ip] = pack2(-r0, -r1);
    }

    // coefficients for this thread's 8 j (4 o x 2 i)
    ull cb01[4][NBASIS], csp01[4], crs01[4];
    #pragma unroll
    for (int q = 0; q < 4; q++) {
        int j0 = (oq * 4 + q) * NIN + lane * 2;
        const float4* p4 = (const float4*)(c_basis + (size_t)j0 * NBASIS);
        float4 f0 = __ldg(&p4[0]);
        float4 f1 = __ldg(&p4[1]);
        float4 f2 = __ldg(&p4[2]);
        cb01[q][0] = pack2(f0.x, f1.z);
        cb01[q][1] = pack2(f0.y, f1.w);
        cb01[q][2] = pack2(f0.z, f2.x);
        cb01[q][3] = pack2(f0.w, f2.y);
        cb01[q][4] = pack2(f1.x, f2.z);
        cb01[q][5] = pack2(f1.y, f2.w);
        csp01[q] = *(const ull*)&c_spl[j0];
        crs01[q] = *(const ull*)&c_res[j0];
    }
    __syncthreads();

    // ---- B: P1(0) ----
    p1(S, 0, b0, batch, t, x);
    __syncthreads();

    ull acc01[4] = {0ull, 0ull, 0ull, 0ull};

    // ---- C: P1(1) + P2(0) ----
    p1(S, 1, b0 + SUB, batch, t, x);
    if (n0 == SUB) p2<true >(S, 0, n0, lane, oq, cb01, csp01, crs01, acc01);
    else           p2<false>(S, 0, n0, lane, oq, cb01, csp01, crs01, acc01);
    __syncthreads();

    // ---- D: EPI1(0) + P2(1) ----
    epi1(S, 0, n0, t);
    if (n1 == SUB) p2<true >(S, 1, n1, lane, oq, cb01, csp01, crs01, acc01);
    else           p2<false>(S, 1, n1, lane, oq, cb01, csp01, crs01, acc01);
    __syncthreads();

    // ---- E: EPI2(0) + EPI1(1) + atomics ----
    epi2(S, 0, n0, b0, t, y_out);
    epi1(S, 1, n1, t);
    #pragma unroll
    for (int q = 0; q < 4; q++) {
        float a0, a1; UNPK(a0, a1, acc01[q]);
        int j = (oq * 4 + q) * NIN + lane * 2;
        atomicAdd(&g_splacc[j],     a0);
        atomicAdd(&g_splacc[j + 1], a1);
    }
    __syncthreads();

    // ---- F: EPI2(1), then grid-wide sync + distributed finalize ----
    epi2(S, 1, n1, b0 + SUB, t, y_out);

    __threadfence();                 // my atomics visible before ticket
    __syncthreads();
    if (t == 0) {
        atomicAdd(&g_ticket, 1u);
        while (*(volatile unsigned int*)&g_ticket < (unsigned)nblocks)
            __nanosleep(64);
    }
    __syncthreads();

    {
        int span = (NJ + nblocks - 1) / nblocks;
        int j0 = blockIdx.x * span;
        int j1 = min(j0 + span, NJ);
        for (int j = j0 + t; j < j1; j += THREADS) {
            float v  = __ldcg(&g_splacc[j]);
            float hi = __ldg(&grid[j * NKNOTS + NKNOTS - 1]);
            float lo = __ldg(&grid[j * NKNOTS]);
            reg_out[j] = v * (inv_batch / (hi - lo + 1e-5f));
            g_splacc[j] = 0.0f;        // reset slice for next replay
        }
    }
    __threadfence();
    __syncthreads();
    if (t == 0) {
        unsigned d = atomicAdd(&g_done, 1u);
        if (d == (unsigned)nblocks - 1) {
            atomicExch(&g_ticket, 0u);
            atomicExch(&g_done, 0u);
        }
    }
}

extern "C" void kernel_launch(void* const* d_in, const int* in_sizes, int n_in,
                              void* d_out, int out_size)
{
    const float* x       = (const float*)d_in[0];
    const float* c_basis = (const float*)d_in[1];
    const float* c_spl   = (const float*)d_in[2];
    const float* c_res   = (const float*)d_in[3];
    const float* grid    = (const float*)d_in[4];

    int batch = in_sizes[0] / NIN;

    float* y_out   = (float*)d_out;                 // (batch, 64)
    float* reg_out = y_out + (size_t)batch * NOUT;  // (64, 64)

    cudaFuncSetAttribute(kan_fused_kernel,
                         cudaFuncAttributeMaxDynamicSharedMemorySize, SMEM_TOTAL);

    int nblocks = (batch + BATCH_TILE - 1) / BATCH_TILE;
    kan_fused_kernel<<<nblocks, THREADS, SMEM_TOTAL>>>(x, c_basis, c_spl, c_res, grid,
                                                       y_out, reg_out, batch,
                                                       1.0f / (float)batch, nblocks);
}